// round 6
// baseline (speedup 1.0000x reference)
#include <cuda_runtime.h>
#include <math.h>

// Problem constants
#define M_TOT 8192   // B*S
#define N_TOT 1024   // HID
#define K_TOT 1024   // HID
#define SEQ   2048
#define NB    4
#define NH    16
#define HD    64

typedef unsigned long long u64;

// ---- packed fp32x2 ops (sm_103a FFMA2 path; ptxas never emits these) ------
#define FFMA2(d, a, b) \
    asm("fma.rn.f32x2 %0, %1, %2, %0;" : "+l"(d) : "l"(a), "l"(b))
#define MUL2(d, b) \
    asm("mul.rn.f32x2 %0, %0, %1;" : "+l"(d) : "l"(b))
#define ADD2(d, a, b) \
    asm("add.rn.f32x2 %0, %1, %2;" : "=l"(d) : "l"(a), "l"(b))
#define PACK2(out, v) \
    asm("mov.b64 %0, {%1, %1};" : "=l"(out) : "r"(__float_as_uint(v)))
#define UNPACK2(lo, hi, in) \
    asm("mov.b64 {%0, %1}, %2;" : "=r"(lo), "=r"(hi) : "l"(in))

// Scratch (device globals: allocation-free per harness rules)
__device__ float g_Q[(size_t)NB * NH * SEQ * HD];
__device__ float g_K[(size_t)NB * NH * SEQ * HD];
__device__ float g_V[(size_t)NB * NH * SEQ * HD];
__device__ float g_X[(size_t)M_TOT * N_TOT];

// ---------------------------------------------------------------------------
// Core SGEMM tile: Y = X @ W^T + bias.
// Block tile 128x128, K-tile 8, 256 threads, 8x8 micro-tile per thread.
// Inner product uses packed FFMA2 (column pairs), exact fp32 per lane.
// Double-buffered shared memory: ONE __syncthreads per K-tile.
// ---------------------------------------------------------------------------
__device__ __forceinline__
void sgemm_tile(const float* __restrict__ X, const float* __restrict__ W,
                const float* __restrict__ bias, float* __restrict__ Y,
                int m0, int n0, bool scatter)
{
    // __align__(16): read through float4 / ulonglong2 — 16B alignment required.
    __shared__ __align__(16) float As[2][8][128];
    __shared__ __align__(16) float Bs[2][8][128];

    const int tid = threadIdx.x;
    const int tx = tid & 15;          // 0..15  -> n micro (8 cols = 4 pairs)
    const int ty = tid >> 4;          // 0..15  -> m micro (8 rows)

    const int lrow = tid >> 1;        // 0..127
    const int lseg = (tid & 1) << 2;  // 0 or 4

    const float* Xp = X + (size_t)(m0 + lrow) * K_TOT + lseg;
    const float* Wp = W + (size_t)(n0 + lrow) * K_TOT + lseg;

    u64 acc2[8][4];                   // [row][col-pair], packed fp32x2
#pragma unroll
    for (int i = 0; i < 8; i++)
#pragma unroll
        for (int j = 0; j < 4; j++) acc2[i][j] = 0ULL;   // (0.0f, 0.0f)

    const int NT = K_TOT / 8;         // 128 K-tiles

    // Prologue: stage tile 0 into buffer 0, prefetch tile 1 into registers.
    float4 xa = *(const float4*)(Xp);
    float4 wb = *(const float4*)(Wp);
    As[0][lseg + 0][lrow] = xa.x;
    As[0][lseg + 1][lrow] = xa.y;
    As[0][lseg + 2][lrow] = xa.z;
    As[0][lseg + 3][lrow] = xa.w;
    Bs[0][lseg + 0][lrow] = wb.x;
    Bs[0][lseg + 1][lrow] = wb.y;
    Bs[0][lseg + 2][lrow] = wb.z;
    Bs[0][lseg + 3][lrow] = wb.w;
    xa = *(const float4*)(Xp + 8);
    wb = *(const float4*)(Wp + 8);
    __syncthreads();

    for (int kt = 0; kt < NT; kt++) {
        const int buf = kt & 1;

        // Stage prefetched tile kt+1 into the other buffer (safe: the barrier
        // ending iter kt-1 guarantees all reads of buf^1 completed).
        if (kt + 1 < NT) {
            As[buf ^ 1][lseg + 0][lrow] = xa.x;
            As[buf ^ 1][lseg + 1][lrow] = xa.y;
            As[buf ^ 1][lseg + 2][lrow] = xa.z;
            As[buf ^ 1][lseg + 3][lrow] = xa.w;
            Bs[buf ^ 1][lseg + 0][lrow] = wb.x;
            Bs[buf ^ 1][lseg + 1][lrow] = wb.y;
            Bs[buf ^ 1][lseg + 2][lrow] = wb.z;
            Bs[buf ^ 1][lseg + 3][lrow] = wb.w;
        }
        // Prefetch tile kt+2 from global (hidden under the FFMA2 block).
        if (kt + 2 < NT) {
            xa = *(const float4*)(Xp + (kt + 2) * 8);
            wb = *(const float4*)(Wp + (kt + 2) * 8);
        }

#pragma unroll
        for (int kk = 0; kk < 8; kk++) {
            // A scalars (warp-broadcast reads: only 2 distinct addrs/warp)
            float4 t0 = *(const float4*)&As[buf][kk][ty * 8];
            float4 t1 = *(const float4*)&As[buf][kk][ty * 8 + 4];
            float a[8] = {t0.x, t0.y, t0.z, t0.w, t1.x, t1.y, t1.z, t1.w};
            // B column pairs, loaded pre-packed (16B-aligned)
            ulonglong2 u0 = *(const ulonglong2*)&Bs[buf][kk][tx * 8];
            ulonglong2 u1 = *(const ulonglong2*)&Bs[buf][kk][tx * 8 + 4];
            u64 b2[4] = {u0.x, u0.y, u1.x, u1.y};
#pragma unroll
            for (int i = 0; i < 8; i++) {
                u64 ap;
                PACK2(ap, a[i]);
                FFMA2(acc2[i][0], ap, b2[0]);
                FFMA2(acc2[i][1], ap, b2[1]);
                FFMA2(acc2[i][2], ap, b2[2]);
                FFMA2(acc2[i][3], ap, b2[3]);
            }
        }
        __syncthreads();
    }

    // Epilogue: packed bias add, 16B stores.
    ulonglong2 bb0 = *(const ulonglong2*)&bias[n0 + tx * 8];
    ulonglong2 bb1 = *(const ulonglong2*)&bias[n0 + tx * 8 + 4];
    u64 bb2[4] = {bb0.x, bb0.y, bb1.x, bb1.y};

#pragma unroll
    for (int i = 0; i < 8; i++) {
        const int m = m0 + ty * 8 + i;
        u64 r[4];
        ADD2(r[0], acc2[i][0], bb2[0]);
        ADD2(r[1], acc2[i][1], bb2[1]);
        ADD2(r[2], acc2[i][2], bb2[2]);
        ADD2(r[3], acc2[i][3], bb2[3]);
        float* p;
        if (!scatter) {
            p = Y + (size_t)m * N_TOT + n0 + tx * 8;
        } else {
            const int b = m >> 11;          // m / 2048
            const int s = m & 2047;
            const int n = n0 + tx * 8;      // 8 cols never straddle a head
            const int h = n >> 6;
            const int d = n & 63;
            p = Y + ((size_t)((b * NH + h) * SEQ + s)) * HD + d;
        }
        ((ulonglong2*)p)[0] = make_ulonglong2(r[0], r[1]);
        ((ulonglong2*)p)[1] = make_ulonglong2(r[2], r[3]);
    }
}

// Fused QKV projection: blockIdx.z selects {Q,K,V}.
__global__ __launch_bounds__(256)
void qkv_proj_kernel(const float* __restrict__ q_in, const float* __restrict__ k_in,
                     const float* __restrict__ v_in,
                     const float* __restrict__ Wq, const float* __restrict__ bq,
                     const float* __restrict__ Wk, const float* __restrict__ bk,
                     const float* __restrict__ Wv, const float* __restrict__ bv,
                     float* __restrict__ Qo, float* __restrict__ Ko,
                     float* __restrict__ Vo)
{
    const int which = blockIdx.z;
    const float* X;  const float* W;  const float* bias;  float* Y;
    if (which == 0)      { X = q_in; W = Wq; bias = bq; Y = Qo; }
    else if (which == 1) { X = k_in; W = Wk; bias = bk; Y = Ko; }
    else                 { X = v_in; W = Wv; bias = bv; Y = Vo; }
    sgemm_tile(X, W, bias, Y, blockIdx.y * 128, blockIdx.x * 128, true);
}

__global__ __launch_bounds__(256)
void out_proj_kernel(const float* __restrict__ X, const float* __restrict__ W,
                     const float* __restrict__ bias, float* __restrict__ Y)
{
    sgemm_tile(X, W, bias, Y, blockIdx.y * 128, blockIdx.x * 128, false);
}

// ---------------------------------------------------------------------------
// Flash attention (fp32, FFMA2 inner loops). One block = 64 queries of one
// (b,h). Tiles of 64 keys. Q,K transposed [d][q] in smem (stride 68; all
// vector-accessed offsets are 16B multiples: 68*4=272, 4*4=16).
// Q pre-scaled by 0.125 (exact). V,P natural (stride 64).
// ---------------------------------------------------------------------------
__global__ __launch_bounds__(256)
void flash_attn_kernel(const float* __restrict__ Q, const float* __restrict__ K,
                       const float* __restrict__ V, const int* __restrict__ mask,
                       float* __restrict__ Xb)
{
    extern __shared__ float sm[];
    float* Qs = sm;                   // 64*68
    float* Ks = Qs + 64 * 68;         // 64*68
    float* Vs = Ks + 64 * 68;         // 64*64  [kk][d]
    float* Ps = Vs + 64 * 64;         // 64*64  [q][kk]
    int*   Mk = (int*)(Ps + 64 * 64); // 64

    const int tid = threadIdx.x;
    const int tx = tid & 15;          // key micro (4 cols = 2 pairs)
    const int ty = tid >> 4;          // query micro (4 rows)
    const int bh = blockIdx.y;
    const int b  = bh >> 4;
    const int h  = bh & 15;
    const int q0 = blockIdx.x * 64;

    const float* Qg = Q + ((size_t)bh * SEQ + q0) * HD;
    const float* Kg = K + (size_t)bh * SEQ * HD;
    const float* Vg = V + (size_t)bh * SEQ * HD;
    const int*   mb = mask + b * SEQ;

    // Load Q tile transposed and pre-scaled: Qs[d][q] = Q[q][d] * 0.125
    for (int i = tid; i < 64 * 64; i += 256) {
        const int q = i >> 6, d = i & 63;
        Qs[d * 68 + q] = Qg[i] * 0.125f;   // i == q*64+d
    }

    u64 o2[4][2];                     // [row][col-pair] packed fp32x2
    float mr[4], lr[4];
#pragma unroll
    for (int i = 0; i < 4; i++) {
        mr[i] = -INFINITY; lr[i] = 0.f;
        o2[i][0] = 0ULL; o2[i][1] = 0ULL;
    }

    for (int kt = 0; kt < SEQ / 64; kt++) {
        const float* Ktile = Kg + (size_t)kt * 64 * HD;
        const float4* Vtile4 = (const float4*)(Vg + (size_t)kt * 64 * HD);
        __syncthreads();
        // K: scalar transposed store (4-way STS conflicts; float4 variant
        // would be 8-way — worse by the bank model).
        for (int i = tid; i < 64 * 64; i += 256) {
            const int r = i >> 6, d = i & 63;
            Ks[d * 68 + r] = Ktile[i];
        }
        // V: natural layout -> vectorized LDG.128/STS.128, conflict-free.
        for (int i = tid; i < 64 * 16; i += 256) {
            ((float4*)Vs)[i] = Vtile4[i];
        }
        if (tid < 64) Mk[tid] = mb[kt * 64 + tid];
        __syncthreads();

        // S = Q K^T  (inner dim d = 64), packed over key pairs
        u64 s2[4][2];
#pragma unroll
        for (int i = 0; i < 4; i++) { s2[i][0] = 0ULL; s2[i][1] = 0ULL; }

#pragma unroll 8
        for (int d = 0; d < 64; d++) {
            float4 a = *(const float4*)&Qs[d * 68 + ty * 4];     // broadcast
            ulonglong2 k2 = *(const ulonglong2*)&Ks[d * 68 + tx * 4];
            u64 ap;
            PACK2(ap, a.x); FFMA2(s2[0][0], ap, k2.x); FFMA2(s2[0][1], ap, k2.y);
            PACK2(ap, a.y); FFMA2(s2[1][0], ap, k2.x); FFMA2(s2[1][1], ap, k2.y);
            PACK2(ap, a.z); FFMA2(s2[2][0], ap, k2.x); FFMA2(s2[2][1], ap, k2.y);
            PACK2(ap, a.w); FFMA2(s2[3][0], ap, k2.x); FFMA2(s2[3][1], ap, k2.y);
        }

        // Unpack to scalars for mask + softmax
        float s[4][4];
#pragma unroll
        for (int i = 0; i < 4; i++) {
            unsigned r0, r1, r2, r3;
            UNPACK2(r0, r1, s2[i][0]);
            UNPACK2(r2, r3, s2[i][1]);
            s[i][0] = __uint_as_float(r0);
            s[i][1] = __uint_as_float(r1);
            s[i][2] = __uint_as_float(r2);
            s[i][3] = __uint_as_float(r3);
        }

        // mask (scale already folded into Q)
#pragma unroll
        for (int j = 0; j < 4; j++) {
            const bool keep = (Mk[tx * 4 + j] != 0);
#pragma unroll
            for (int i = 0; i < 4; i++)
                s[i][j] = keep ? s[i][j] : -1.0e10f;
        }

        // online softmax per query row (reduce across the 16 tx lanes).
        // All-masked tiles: p=exp(0)=1 per key; the bogus mass is later
        // cancelled by alpha -> 0, or (if the whole row is masked) yields the
        // reference's uniform softmax exactly.
#pragma unroll
        for (int i = 0; i < 4; i++) {
            float tm = fmaxf(fmaxf(s[i][0], s[i][1]), fmaxf(s[i][2], s[i][3]));
            tm = fmaxf(tm, __shfl_xor_sync(0xffffffffu, tm, 1));
            tm = fmaxf(tm, __shfl_xor_sync(0xffffffffu, tm, 2));
            tm = fmaxf(tm, __shfl_xor_sync(0xffffffffu, tm, 4));
            tm = fmaxf(tm, __shfl_xor_sync(0xffffffffu, tm, 8));
            const float mn = fmaxf(mr[i], tm);
            const float alpha = __expf(mr[i] - mn);
            mr[i] = mn;
            float rs = 0.f;
#pragma unroll
            for (int j = 0; j < 4; j++) {
                const float p = __expf(s[i][j] - mn);
                s[i][j] = p;
                rs += p;
            }
            rs += __shfl_xor_sync(0xffffffffu, rs, 1);
            rs += __shfl_xor_sync(0xffffffffu, rs, 2);
            rs += __shfl_xor_sync(0xffffffffu, rs, 4);
            rs += __shfl_xor_sync(0xffffffffu, rs, 8);
            lr[i] = lr[i] * alpha + rs;
            u64 al;
            PACK2(al, alpha);
            MUL2(o2[i][0], al);
            MUL2(o2[i][1], al);
            *(float4*)&Ps[(ty * 4 + i) * 64 + tx * 4] =
                make_float4(s[i][0], s[i][1], s[i][2], s[i][3]);
        }
        __syncthreads();

        // O += P V   (inner dim kk = 64), packed over d pairs
#pragma unroll 8
        for (int kk = 0; kk < 64; kk++) {
            ulonglong2 v2 = *(const ulonglong2*)&Vs[kk * 64 + tx * 4];
            const float p0 = Ps[(ty * 4 + 0) * 64 + kk];   // broadcast reads
            const float p1 = Ps[(ty * 4 + 1) * 64 + kk];
            const float p2 = Ps[(ty * 4 + 2) * 64 + kk];
            const float p3 = Ps[(ty * 4 + 3) * 64 + kk];
            u64 pp;
            PACK2(pp, p0); FFMA2(o2[0][0], pp, v2.x); FFMA2(o2[0][1], pp, v2.y);
            PACK2(pp, p1); FFMA2(o2[1][0], pp, v2.x); FFMA2(o2[1][1], pp, v2.y);
            PACK2(pp, p2); FFMA2(o2[2][0], pp, v2.x); FFMA2(o2[2][1], pp, v2.y);
            PACK2(pp, p3); FFMA2(o2[3][0], pp, v2.x); FFMA2(o2[3][1], pp, v2.y);
        }
    }

    // epilogue: normalize, write to [B, S, HID] with feature = h*64 + d
#pragma unroll
    for (int i = 0; i < 4; i++) {
        const float inv = 1.0f / lr[i];
        unsigned r0, r1, r2, r3;
        UNPACK2(r0, r1, o2[i][0]);
        UNPACK2(r2, r3, o2[i][1]);
        const int q = q0 + ty * 4 + i;
        float* p = Xb + ((size_t)(b * SEQ + q)) * N_TOT + h * HD + tx * 4;
        *(float4*)p = make_float4(__uint_as_float(r0) * inv,
                                  __uint_as_float(r1) * inv,
                                  __uint_as_float(r2) * inv,
                                  __uint_as_float(r3) * inv);
    }
}

// ---------------------------------------------------------------------------
// Launch
// ---------------------------------------------------------------------------
extern "C" void kernel_launch(void* const* d_in, const int* in_sizes, int n_in,
                              void* d_out, int out_size)
{
    const float* q    = (const float*)d_in[0];
    const float* k    = (const float*)d_in[1];
    const float* v    = (const float*)d_in[2];
    const int*   mask = (const int*)  d_in[3];
    const float* Wq   = (const float*)d_in[4];
    const float* bq   = (const float*)d_in[5];
    const float* Wk   = (const float*)d_in[6];
    const float* bk   = (const float*)d_in[7];
    const float* Wv   = (const float*)d_in[8];
    const float* bv   = (const float*)d_in[9];
    const float* Wo   = (const float*)d_in[10];
    const float* bo   = (const float*)d_in[11];
    float* out = (float*)d_out;

    void *pq, *pk, *pv, *px;
    cudaGetSymbolAddress(&pq, g_Q);
    cudaGetSymbolAddress(&pk, g_K);
    cudaGetSymbolAddress(&pv, g_V);
    cudaGetSymbolAddress(&px, g_X);

    // Fused Q/K/V projections: one launch, 1536 CTAs.
    dim3 gqkv(N_TOT / 128, M_TOT / 128, 3);   // (8, 64, 3)
    qkv_proj_kernel<<<gqkv, 256>>>(q, k, v, Wq, bq, Wk, bk, Wv, bv,
                                   (float*)pq, (float*)pk, (float*)pv);

    const int smem_bytes = (2 * 64 * 68 + 2 * 64 * 64) * 4 + 64 * 4;  // ~67.8 KB
    cudaFuncSetAttribute(flash_attn_kernel,
                         cudaFuncAttributeMaxDynamicSharedMemorySize, smem_bytes);
    flash_attn_kernel<<<dim3(SEQ / 64, NB * NH), 256, smem_bytes>>>(
        (const float*)pq, (const float*)pk, (const float*)pv, mask, (float*)px);

    dim3 go(N_TOT / 128, M_TOT / 128);        // (8, 64)
    out_proj_kernel<<<go, 256>>>((const float*)px, Wo, bo, out);
}

// round 10
// speedup vs baseline: 1.1060x; 1.1060x over previous
#include <cuda_runtime.h>
#include <math.h>

// Problem constants
#define M_TOT 8192   // B*S
#define N_TOT 1024   // HID
#define K_TOT 1024   // HID
#define SEQ   2048
#define NB    4
#define NH    16
#define HD    64

typedef unsigned long long u64;

// ---- packed fp32x2 ops (sm_103a FFMA2 path; ptxas never emits these) ------
#define FFMA2(d, a, b) \
    asm("fma.rn.f32x2 %0, %1, %2, %0;" : "+l"(d) : "l"(a), "l"(b))
#define MUL2(d, b) \
    asm("mul.rn.f32x2 %0, %0, %1;" : "+l"(d) : "l"(b))
#define ADD2(d, a, b) \
    asm("add.rn.f32x2 %0, %1, %2;" : "=l"(d) : "l"(a), "l"(b))
#define PACK2(out, v) \
    asm("mov.b64 %0, {%1, %1};" : "=l"(out) : "r"(__float_as_uint(v)))
#define UNPACK2(lo, hi, in) \
    asm("mov.b64 {%0, %1}, %2;" : "=r"(lo), "=r"(hi) : "l"(in))

// Scratch (device globals: allocation-free per harness rules)
__device__ float g_Q[(size_t)NB * NH * SEQ * HD];
__device__ float g_K[(size_t)NB * NH * SEQ * HD];
__device__ float g_V[(size_t)NB * NH * SEQ * HD];
__device__ float g_X[(size_t)M_TOT * N_TOT];

// ---------------------------------------------------------------------------
// Core SGEMM tile: Y = X @ W^T + bias.
// Block tile 128x128, K-tile 8, 256 threads, 8x8 micro-tile per thread.
// Column micro-tile is SPLIT: cols {tx*4..tx*4+3} and {64+tx*4..64+tx*4+3}.
// -> Bs compute reads are lane-consecutive 16B chunks: conflict-free LDS.128
//    (the contiguous tx*8 layout had an inherent 4-way bank conflict: 32B
//    lane stride spans 512B = 4x the 128B bank span; this was the measured
//    L1=84.1% bottleneck in the R6 profile).
// Inner product uses packed FFMA2 (column pairs), exact fp32 per lane.
// Double-buffered shared memory: ONE __syncthreads per K-tile.
// ---------------------------------------------------------------------------
__device__ __forceinline__
void sgemm_tile(const float* __restrict__ X, const float* __restrict__ W,
                const float* __restrict__ bias, float* __restrict__ Y,
                int m0, int n0, bool scatter)
{
    // __align__(16): read through float4 / ulonglong2 — 16B alignment required.
    __shared__ __align__(16) float As[2][8][128];
    __shared__ __align__(16) float Bs[2][8][128];

    const int tid = threadIdx.x;
    const int tx = tid & 15;          // 0..15  -> n micro (2x4 split cols)
    const int ty = tid >> 4;          // 0..15  -> m micro (8 rows)

    const int lrow = tid >> 1;        // 0..127
    const int lseg = (tid & 1) << 2;  // 0 or 4

    const float* Xp = X + (size_t)(m0 + lrow) * K_TOT + lseg;
    const float* Wp = W + (size_t)(n0 + lrow) * K_TOT + lseg;

    u64 acc2[8][4];                   // [row][col-pair]; pairs 0,1 = cols tx*4..+3,
                                      //                  pairs 2,3 = cols 64+tx*4..+3
#pragma unroll
    for (int i = 0; i < 8; i++)
#pragma unroll
        for (int j = 0; j < 4; j++) acc2[i][j] = 0ULL;   // (0.0f, 0.0f)

    const int NT = K_TOT / 8;         // 128 K-tiles

    // Prologue: stage tile 0 into buffer 0, prefetch tile 1 into registers.
    float4 xa = *(const float4*)(Xp);
    float4 wb = *(const float4*)(Wp);
    As[0][lseg + 0][lrow] = xa.x;
    As[0][lseg + 1][lrow] = xa.y;
    As[0][lseg + 2][lrow] = xa.z;
    As[0][lseg + 3][lrow] = xa.w;
    Bs[0][lseg + 0][lrow] = wb.x;
    Bs[0][lseg + 1][lrow] = wb.y;
    Bs[0][lseg + 2][lrow] = wb.z;
    Bs[0][lseg + 3][lrow] = wb.w;
    xa = *(const float4*)(Xp + 8);
    wb = *(const float4*)(Wp + 8);
    __syncthreads();

    for (int kt = 0; kt < NT; kt++) {
        const int buf = kt & 1;

        // Stage prefetched tile kt+1 into the other buffer (safe: the barrier
        // ending iter kt-1 guarantees all reads of buf^1 completed).
        if (kt + 1 < NT) {
            As[buf ^ 1][lseg + 0][lrow] = xa.x;
            As[buf ^ 1][lseg + 1][lrow] = xa.y;
            As[buf ^ 1][lseg + 2][lrow] = xa.z;
            As[buf ^ 1][lseg + 3][lrow] = xa.w;
            Bs[buf ^ 1][lseg + 0][lrow] = wb.x;
            Bs[buf ^ 1][lseg + 1][lrow] = wb.y;
            Bs[buf ^ 1][lseg + 2][lrow] = wb.z;
            Bs[buf ^ 1][lseg + 3][lrow] = wb.w;
        }
        // Prefetch tile kt+2 from global (hidden under the FFMA2 block).
        if (kt + 2 < NT) {
            xa = *(const float4*)(Xp + (kt + 2) * 8);
            wb = *(const float4*)(Wp + (kt + 2) * 8);
        }

#pragma unroll
        for (int kk = 0; kk < 8; kk++) {
            // A scalars (warp-broadcast reads: 2 distinct 16B addrs/warp at
            // disjoint banks -> conflict-free)
            float4 t0 = *(const float4*)&As[buf][kk][ty * 8];
            float4 t1 = *(const float4*)&As[buf][kk][ty * 8 + 4];
            float a[8] = {t0.x, t0.y, t0.z, t0.w, t1.x, t1.y, t1.z, t1.w};
            // B split-column pairs: lane-consecutive 16B -> conflict-free
            ulonglong2 u0 = *(const ulonglong2*)&Bs[buf][kk][tx * 4];
            ulonglong2 u1 = *(const ulonglong2*)&Bs[buf][kk][64 + tx * 4];
            u64 b2[4] = {u0.x, u0.y, u1.x, u1.y};
#pragma unroll
            for (int i = 0; i < 8; i++) {
                u64 ap;
                PACK2(ap, a[i]);
                FFMA2(acc2[i][0], ap, b2[0]);
                FFMA2(acc2[i][1], ap, b2[1]);
                FFMA2(acc2[i][2], ap, b2[2]);
                FFMA2(acc2[i][3], ap, b2[3]);
            }
        }
        __syncthreads();
    }

    // Epilogue: packed bias add, two 16B stores per row (split columns).
    ulonglong2 bb0 = *(const ulonglong2*)&bias[n0 + tx * 4];
    ulonglong2 bb1 = *(const ulonglong2*)&bias[n0 + 64 + tx * 4];
    u64 bb2[4] = {bb0.x, bb0.y, bb1.x, bb1.y};

#pragma unroll
    for (int i = 0; i < 8; i++) {
        const int m = m0 + ty * 8 + i;
        u64 r[4];
        ADD2(r[0], acc2[i][0], bb2[0]);
        ADD2(r[1], acc2[i][1], bb2[1]);
        ADD2(r[2], acc2[i][2], bb2[2]);
        ADD2(r[3], acc2[i][3], bb2[3]);
        const int n_a = n0 + tx * 4;         // first 4-col group
        const int n_b = n_a + 64;            // second 4-col group
        float *pa, *pb;
        if (!scatter) {
            pa = Y + (size_t)m * N_TOT + n_a;
            pb = Y + (size_t)m * N_TOT + n_b;
        } else {
            const int b = m >> 11;           // m / 2048
            const int s = m & 2047;
            // 4-col groups never straddle a head (4 | 64)
            pa = Y + ((size_t)((b * NH + (n_a >> 6)) * SEQ + s)) * HD + (n_a & 63);
            pb = Y + ((size_t)((b * NH + (n_b >> 6)) * SEQ + s)) * HD + (n_b & 63);
        }
        *(ulonglong2*)pa = make_ulonglong2(r[0], r[1]);
        *(ulonglong2*)pb = make_ulonglong2(r[2], r[3]);
    }
}

// Fused QKV projection: blockIdx.z selects {Q,K,V}.
__global__ __launch_bounds__(256)
void qkv_proj_kernel(const float* __restrict__ q_in, const float* __restrict__ k_in,
                     const float* __restrict__ v_in,
                     const float* __restrict__ Wq, const float* __restrict__ bq,
                     const float* __restrict__ Wk, const float* __restrict__ bk,
                     const float* __restrict__ Wv, const float* __restrict__ bv,
                     float* __restrict__ Qo, float* __restrict__ Ko,
                     float* __restrict__ Vo)
{
    const int which = blockIdx.z;
    const float* X;  const float* W;  const float* bias;  float* Y;
    if (which == 0)      { X = q_in; W = Wq; bias = bq; Y = Qo; }
    else if (which == 1) { X = k_in; W = Wk; bias = bk; Y = Ko; }
    else                 { X = v_in; W = Wv; bias = bv; Y = Vo; }
    sgemm_tile(X, W, bias, Y, blockIdx.y * 128, blockIdx.x * 128, true);
}

__global__ __launch_bounds__(256)
void out_proj_kernel(const float* __restrict__ X, const float* __restrict__ W,
                     const float* __restrict__ bias, float* __restrict__ Y)
{
    sgemm_tile(X, W, bias, Y, blockIdx.y * 128, blockIdx.x * 128, false);
}

// ---------------------------------------------------------------------------
// Flash attention (fp32, FFMA2 inner loops). One block = 64 queries of one
// (b,h). Tiles of 64 keys. Q,K transposed [d][q] in smem (stride 68; all
// vector-accessed offsets are 16B multiples). Smem compute reads are already
// conflict-free (tx*4 lane-consecutive chunks + ty-broadcasts).
// Q pre-scaled by 0.125 (exact). V,P natural (stride 64).
// At the FFMA2 issue roofline: ~1024 FFMA2/thread/tile vs ~400 cyc overhead.
// ---------------------------------------------------------------------------
__global__ __launch_bounds__(256)
void flash_attn_kernel(const float* __restrict__ Q, const float* __restrict__ K,
                       const float* __restrict__ V, const int* __restrict__ mask,
                       float* __restrict__ Xb)
{
    extern __shared__ float sm[];
    float* Qs = sm;                   // 64*68
    float* Ks = Qs + 64 * 68;         // 64*68
    float* Vs = Ks + 64 * 68;         // 64*64  [kk][d]
    float* Ps = Vs + 64 * 64;         // 64*64  [q][kk]
    int*   Mk = (int*)(Ps + 64 * 64); // 64

    const int tid = threadIdx.x;
    const int tx = tid & 15;          // key micro (4 cols = 2 pairs)
    const int ty = tid >> 4;          // query micro (4 rows)
    const int bh = blockIdx.y;
    const int b  = bh >> 4;
    const int h  = bh & 15;
    const int q0 = blockIdx.x * 64;

    const float* Qg = Q + ((size_t)bh * SEQ + q0) * HD;
    const float* Kg = K + (size_t)bh * SEQ * HD;
    const float* Vg = V + (size_t)bh * SEQ * HD;
    const int*   mb = mask + b * SEQ;

    // Load Q tile transposed and pre-scaled: Qs[d][q] = Q[q][d] * 0.125
    for (int i = tid; i < 64 * 64; i += 256) {
        const int q = i >> 6, d = i & 63;
        Qs[d * 68 + q] = Qg[i] * 0.125f;   // i == q*64+d
    }

    u64 o2[4][2];                     // [row][col-pair] packed fp32x2
    float mr[4], lr[4];
#pragma unroll
    for (int i = 0; i < 4; i++) {
        mr[i] = -INFINITY; lr[i] = 0.f;
        o2[i][0] = 0ULL; o2[i][1] = 0ULL;
    }

    for (int kt = 0; kt < SEQ / 64; kt++) {
        const float* Ktile = Kg + (size_t)kt * 64 * HD;
        const float4* Vtile4 = (const float4*)(Vg + (size_t)kt * 64 * HD);
        __syncthreads();
        // K: scalar transposed store (4-way STS conflicts; float4 variant
        // would be 8-way — worse by the bank model). Staging cost is ~3% of
        // the tile's compute time; not worth restructuring.
        for (int i = tid; i < 64 * 64; i += 256) {
            const int r = i >> 6, d = i & 63;
            Ks[d * 68 + r] = Ktile[i];
        }
        // V: natural layout -> vectorized LDG.128/STS.128, conflict-free.
        for (int i = tid; i < 64 * 16; i += 256) {
            ((float4*)Vs)[i] = Vtile4[i];
        }
        if (tid < 64) Mk[tid] = mb[kt * 64 + tid];
        __syncthreads();

        // S = Q K^T  (inner dim d = 64), packed over key pairs
        u64 s2[4][2];
#pragma unroll
        for (int i = 0; i < 4; i++) { s2[i][0] = 0ULL; s2[i][1] = 0ULL; }

#pragma unroll 8
        for (int d = 0; d < 64; d++) {
            float4 a = *(const float4*)&Qs[d * 68 + ty * 4];     // broadcast
            ulonglong2 k2 = *(const ulonglong2*)&Ks[d * 68 + tx * 4];
            u64 ap;
            PACK2(ap, a.x); FFMA2(s2[0][0], ap, k2.x); FFMA2(s2[0][1], ap, k2.y);
            PACK2(ap, a.y); FFMA2(s2[1][0], ap, k2.x); FFMA2(s2[1][1], ap, k2.y);
            PACK2(ap, a.z); FFMA2(s2[2][0], ap, k2.x); FFMA2(s2[2][1], ap, k2.y);
            PACK2(ap, a.w); FFMA2(s2[3][0], ap, k2.x); FFMA2(s2[3][1], ap, k2.y);
        }

        // Unpack to scalars for mask + softmax
        float s[4][4];
#pragma unroll
        for (int i = 0; i < 4; i++) {
            unsigned r0, r1, r2, r3;
            UNPACK2(r0, r1, s2[i][0]);
            UNPACK2(r2, r3, s2[i][1]);
            s[i][0] = __uint_as_float(r0);
            s[i][1] = __uint_as_float(r1);
            s[i][2] = __uint_as_float(r2);
            s[i][3] = __uint_as_float(r3);
        }

        // mask (scale already folded into Q)
#pragma unroll
        for (int j = 0; j < 4; j++) {
            const bool keep = (Mk[tx * 4 + j] != 0);
#pragma unroll
            for (int i = 0; i < 4; i++)
                s[i][j] = keep ? s[i][j] : -1.0e10f;
        }

        // online softmax per query row (reduce across the 16 tx lanes).
#pragma unroll
        for (int i = 0; i < 4; i++) {
            float tm = fmaxf(fmaxf(s[i][0], s[i][1]), fmaxf(s[i][2], s[i][3]));
            tm = fmaxf(tm, __shfl_xor_sync(0xffffffffu, tm, 1));
            tm = fmaxf(tm, __shfl_xor_sync(0xffffffffu, tm, 2));
            tm = fmaxf(tm, __shfl_xor_sync(0xffffffffu, tm, 4));
            tm = fmaxf(tm, __shfl_xor_sync(0xffffffffu, tm, 8));
            const float mn = fmaxf(mr[i], tm);
            const float alpha = __expf(mr[i] - mn);
            mr[i] = mn;
            float rs = 0.f;
#pragma unroll
            for (int j = 0; j < 4; j++) {
                const float p = __expf(s[i][j] - mn);
                s[i][j] = p;
                rs += p;
            }
            rs += __shfl_xor_sync(0xffffffffu, rs, 1);
            rs += __shfl_xor_sync(0xffffffffu, rs, 2);
            rs += __shfl_xor_sync(0xffffffffu, rs, 4);
            rs += __shfl_xor_sync(0xffffffffu, rs, 8);
            lr[i] = lr[i] * alpha + rs;
            u64 al;
            PACK2(al, alpha);
            MUL2(o2[i][0], al);
            MUL2(o2[i][1], al);
            *(float4*)&Ps[(ty * 4 + i) * 64 + tx * 4] =
                make_float4(s[i][0], s[i][1], s[i][2], s[i][3]);
        }
        __syncthreads();

        // O += P V   (inner dim kk = 64), packed over d pairs
#pragma unroll 8
        for (int kk = 0; kk < 64; kk++) {
            ulonglong2 v2 = *(const ulonglong2*)&Vs[kk * 64 + tx * 4];
            const float p0 = Ps[(ty * 4 + 0) * 64 + kk];   // broadcast reads
            const float p1 = Ps[(ty * 4 + 1) * 64 + kk];
            const float p2 = Ps[(ty * 4 + 2) * 64 + kk];
            const float p3 = Ps[(ty * 4 + 3) * 64 + kk];
            u64 pp;
            PACK2(pp, p0); FFMA2(o2[0][0], pp, v2.x); FFMA2(o2[0][1], pp, v2.y);
            PACK2(pp, p1); FFMA2(o2[1][0], pp, v2.x); FFMA2(o2[1][1], pp, v2.y);
            PACK2(pp, p2); FFMA2(o2[2][0], pp, v2.x); FFMA2(o2[2][1], pp, v2.y);
            PACK2(pp, p3); FFMA2(o2[3][0], pp, v2.x); FFMA2(o2[3][1], pp, v2.y);
        }
    }

    // epilogue: normalize, write to [B, S, HID] with feature = h*64 + d
#pragma unroll
    for (int i = 0; i < 4; i++) {
        const float inv = 1.0f / lr[i];
        unsigned r0, r1, r2, r3;
        UNPACK2(r0, r1, o2[i][0]);
        UNPACK2(r2, r3, o2[i][1]);
        const int q = q0 + ty * 4 + i;
        float* p = Xb + ((size_t)(b * SEQ + q)) * N_TOT + h * HD + tx * 4;
        *(float4*)p = make_float4(__uint_as_float(r0) * inv,
                                  __uint_as_float(r1) * inv,
                                  __uint_as_float(r2) * inv,
                                  __uint_as_float(r3) * inv);
    }
}

// ---------------------------------------------------------------------------
// Launch
// ---------------------------------------------------------------------------
extern "C" void kernel_launch(void* const* d_in, const int* in_sizes, int n_in,
                              void* d_out, int out_size)
{
    const float* q    = (const float*)d_in[0];
    const float* k    = (const float*)d_in[1];
    const float* v    = (const float*)d_in[2];
    const int*   mask = (const int*)  d_in[3];
    const float* Wq   = (const float*)d_in[4];
    const float* bq   = (const float*)d_in[5];
    const float* Wk   = (const float*)d_in[6];
    const float* bk   = (const float*)d_in[7];
    const float* Wv   = (const float*)d_in[8];
    const float* bv   = (const float*)d_in[9];
    const float* Wo   = (const float*)d_in[10];
    const float* bo   = (const float*)d_in[11];
    float* out = (float*)d_out;

    void *pq, *pk, *pv, *px;
    cudaGetSymbolAddress(&pq, g_Q);
    cudaGetSymbolAddress(&pk, g_K);
    cudaGetSymbolAddress(&pv, g_V);
    cudaGetSymbolAddress(&px, g_X);

    // Fused Q/K/V projections: one launch, 1536 CTAs.
    dim3 gqkv(N_TOT / 128, M_TOT / 128, 3);   // (8, 64, 3)
    qkv_proj_kernel<<<gqkv, 256>>>(q, k, v, Wq, bq, Wk, bk, Wv, bv,
                                   (float*)pq, (float*)pk, (float*)pv);

    const int smem_bytes = (2 * 64 * 68 + 2 * 64 * 64) * 4 + 64 * 4;  // ~67.8 KB
    cudaFuncSetAttribute(flash_attn_kernel,
                         cudaFuncAttributeMaxDynamicSharedMemorySize, smem_bytes);
    flash_attn_kernel<<<dim3(SEQ / 64, NB * NH), 256, smem_bytes>>>(
        (const float*)pq, (const float*)pk, (const float*)pv, mask, (float*)px);

    dim3 go(N_TOT / 128, M_TOT / 128);        // (8, 64)
    out_proj_kernel<<<go, 256>>>((const float*)px, Wo, bo, out);
}

// round 17
// speedup vs baseline: 1.4824x; 1.3402x over previous
#include <cuda_runtime.h>
#include <cuda_bf16.h>
#include <math.h>
#include <stdint.h>

// Problem constants
#define M_TOT 8192   // B*S
#define N_TOT 1024   // HID
#define K_TOT 1024   // HID
#define SEQ   2048
#define NB    4
#define NH    16
#define HD    64

typedef unsigned long long u64;

// ---- packed fp32x2 ops (flash attention path) -----------------------------
#define FFMA2(d, a, b) \
    asm("fma.rn.f32x2 %0, %1, %2, %0;" : "+l"(d) : "l"(a), "l"(b))
#define MUL2(d, b) \
    asm("mul.rn.f32x2 %0, %0, %1;" : "+l"(d) : "l"(b))
#define PACK2(out, v) \
    asm("mov.b64 %0, {%1, %1};" : "=l"(out) : "r"(__float_as_uint(v)))
#define UNPACK2(lo, hi, in) \
    asm("mov.b64 {%0, %1}, %2;" : "=r"(lo), "=r"(hi) : "l"(in))

// Scratch (device globals: allocation-free per harness rules)
__device__ float g_Q[(size_t)NB * NH * SEQ * HD];
__device__ float g_K[(size_t)NB * NH * SEQ * HD];
__device__ float g_V[(size_t)NB * NH * SEQ * HD];
__device__ float g_X[(size_t)M_TOT * N_TOT];

// ===========================================================================
// mma.sync helpers (sm_80-class path: ldmatrix + HMMA; legal at compute_103)
// ===========================================================================
__device__ __forceinline__ uint32_t smem_u32(const void* p) {
    uint32_t a;
    asm("{ .reg .u64 t; cvta.to.shared.u64 t, %1; cvt.u32.u64 %0, t; }"
        : "=r"(a) : "l"(p));
    return a;
}
__device__ __forceinline__ void ldsm_x4(uint32_t addr, uint32_t* r) {
    asm volatile("ldmatrix.sync.aligned.m8n8.x4.shared.b16 {%0,%1,%2,%3}, [%4];"
                 : "=r"(r[0]), "=r"(r[1]), "=r"(r[2]), "=r"(r[3]) : "r"(addr));
}
__device__ __forceinline__ void ldsm_x2(uint32_t addr, uint32_t* r) {
    asm volatile("ldmatrix.sync.aligned.m8n8.x2.shared.b16 {%0,%1}, [%2];"
                 : "=r"(r[0]), "=r"(r[1]) : "r"(addr));
}
__device__ __forceinline__ void mma16816(float* d, const uint32_t* a,
                                         const uint32_t* b) {
    asm volatile(
        "mma.sync.aligned.m16n8k16.row.col.f32.bf16.bf16.f32 "
        "{%0,%1,%2,%3}, {%4,%5,%6,%7}, {%8,%9}, {%0,%1,%2,%3};"
        : "+f"(d[0]), "+f"(d[1]), "+f"(d[2]), "+f"(d[3])
        : "r"(a[0]), "r"(a[1]), "r"(a[2]), "r"(a[3]), "r"(b[0]), "r"(b[1]));
}

// SMEM layout: 4 padded bf16 tiles [128 rows][72 cols] (144B rows: 16B-aligned
// ldmatrix addrs, +4-bank row skew -> conflict-free, no swizzle needed).
#define MM_ROWB   144
#define MM_TILE   (128 * MM_ROWB)     // 18432 B
#define MM_A1     0
#define MM_A2     (MM_TILE)
#define MM_B1     (2 * MM_TILE)
#define MM_B2     (3 * MM_TILE)
#define MM_TOTAL  (4 * MM_TILE)       // 73728 B

// pack 4 bf16 into 8 bytes and store to smem
__device__ __forceinline__ void st_bf16x4(char* p, __nv_bfloat16 a, __nv_bfloat16 b,
                                          __nv_bfloat16 c, __nv_bfloat16 d) {
    __nv_bfloat162 p0 = __halves2bfloat162(a, b);
    __nv_bfloat162 p1 = __halves2bfloat162(c, d);
    uint2 u;
    u.x = *reinterpret_cast<uint32_t*>(&p0);
    u.y = *reinterpret_cast<uint32_t*>(&p1);
    *reinterpret_cast<uint2*>(p) = u;
}

// ---------------------------------------------------------------------------
// mma.sync GEMM tile: Y = X @ W^T + bias. CTA tile 128x128, 256 threads,
// 8 warps in 2(m) x 4(n), warp tile 64x32. fp32-accurate via bf16x2 split
// (3 MMA passes: A1B1 + A1B2 + A2B1), fp32 register accumulators.
// K staged in 16 chunks of 64 (fp32 -> hi/lo bf16 during staging).
// ---------------------------------------------------------------------------
__device__ __forceinline__
void mma_gemm_tile(const float* __restrict__ X, const float* __restrict__ W,
                   const float* __restrict__ bias, float* __restrict__ Y,
                   int m0, int n0, bool scatter)
{
    extern __shared__ char sm[];
    const uint32_t smb = smem_u32(sm);
    const int tid  = threadIdx.x;
    const int w    = tid >> 5;
    const int lane = tid & 31;
    const int wm   = (w >> 2) * 64;   // warp m origin within tile
    const int wn   = (w & 3) * 32;    // warp n origin within tile

    // ldmatrix per-lane address components
    const uint32_t a_off = (uint32_t)((lane & 15) * MM_ROWB + (lane >> 4) * 16);
    const uint32_t b_off = (uint32_t)((lane & 7) * MM_ROWB + ((lane >> 3) & 1) * 16);

    float acc[4][4][4];
#pragma unroll
    for (int mt = 0; mt < 4; mt++)
#pragma unroll
        for (int nt = 0; nt < 4; nt++)
#pragma unroll
            for (int e = 0; e < 4; e++) acc[mt][nt][e] = 0.f;

    for (int c = 0; c < 16; c++) {
        const int k0 = c * 64;
        if (c) __syncthreads();       // previous compute done before overwrite

        // ---- stage chunk c: split fp32 -> bf16 hi/lo into padded tiles ----
#pragma unroll
        for (int i = 0; i < 8; i++) {
            const int idx = i * 256 + tid;          // 0..2047
            const int r = idx >> 4, f = idx & 15;   // row, float4-within-row
            const uint32_t off = (uint32_t)(r * MM_ROWB + f * 8);
            {
                float4 x = ((const float4*)(X + (size_t)(m0 + r) * K_TOT + k0))[f];
                __nv_bfloat16 h0 = __float2bfloat16(x.x), h1 = __float2bfloat16(x.y);
                __nv_bfloat16 h2 = __float2bfloat16(x.z), h3 = __float2bfloat16(x.w);
                __nv_bfloat16 l0 = __float2bfloat16(x.x - __bfloat162float(h0));
                __nv_bfloat16 l1 = __float2bfloat16(x.y - __bfloat162float(h1));
                __nv_bfloat16 l2 = __float2bfloat16(x.z - __bfloat162float(h2));
                __nv_bfloat16 l3 = __float2bfloat16(x.w - __bfloat162float(h3));
                st_bf16x4(sm + MM_A1 + off, h0, h1, h2, h3);
                st_bf16x4(sm + MM_A2 + off, l0, l1, l2, l3);
            }
            {
                float4 x = ((const float4*)(W + (size_t)(n0 + r) * K_TOT + k0))[f];
                __nv_bfloat16 h0 = __float2bfloat16(x.x), h1 = __float2bfloat16(x.y);
                __nv_bfloat16 h2 = __float2bfloat16(x.z), h3 = __float2bfloat16(x.w);
                __nv_bfloat16 l0 = __float2bfloat16(x.x - __bfloat162float(h0));
                __nv_bfloat16 l1 = __float2bfloat16(x.y - __bfloat162float(h1));
                __nv_bfloat16 l2 = __float2bfloat16(x.z - __bfloat162float(h2));
                __nv_bfloat16 l3 = __float2bfloat16(x.w - __bfloat162float(h3));
                st_bf16x4(sm + MM_B1 + off, h0, h1, h2, h3);
                st_bf16x4(sm + MM_B2 + off, l0, l1, l2, l3);
            }
        }
        __syncthreads();

        // ---- compute: 4 k16-steps x (A1B1 + A1B2 + A2B1) ------------------
#pragma unroll
        for (int ks = 0; ks < 4; ks++) {
            const uint32_t kb = (uint32_t)(ks * 32);   // 16 bf16 = 32 bytes
            uint32_t b1f[4][2], b2f[4][2], af[4][4];
#pragma unroll
            for (int nt = 0; nt < 4; nt++)
                ldsm_x2(smb + MM_B1 + (uint32_t)((wn + nt * 8) * MM_ROWB) + b_off + kb,
                        b1f[nt]);
#pragma unroll
            for (int nt = 0; nt < 4; nt++)
                ldsm_x2(smb + MM_B2 + (uint32_t)((wn + nt * 8) * MM_ROWB) + b_off + kb,
                        b2f[nt]);
#pragma unroll
            for (int mt = 0; mt < 4; mt++)
                ldsm_x4(smb + MM_A1 + (uint32_t)((wm + mt * 16) * MM_ROWB) + a_off + kb,
                        af[mt]);
#pragma unroll
            for (int mt = 0; mt < 4; mt++)
#pragma unroll
                for (int nt = 0; nt < 4; nt++)
                    mma16816(acc[mt][nt], af[mt], b1f[nt]);
#pragma unroll
            for (int mt = 0; mt < 4; mt++)
#pragma unroll
                for (int nt = 0; nt < 4; nt++)
                    mma16816(acc[mt][nt], af[mt], b2f[nt]);
#pragma unroll
            for (int mt = 0; mt < 4; mt++)
                ldsm_x4(smb + MM_A2 + (uint32_t)((wm + mt * 16) * MM_ROWB) + a_off + kb,
                        af[mt]);
#pragma unroll
            for (int mt = 0; mt < 4; mt++)
#pragma unroll
                for (int nt = 0; nt < 4; nt++)
                    mma16816(acc[mt][nt], af[mt], b1f[nt]);
        }
    }

    // ---- epilogue: D fragment -> global, + bias ---------------------------
    // Fragment map (m16n8): d0 @ (r, c), d1 @ (r, c+1), d2 @ (r+8, c), d3 @ (r+8, c+1)
    // with r = lane>>2, c = (lane&3)*2.
    const int fr = lane >> 2;
    const int fc = (lane & 3) * 2;
    float2 bb[4];
#pragma unroll
    for (int nt = 0; nt < 4; nt++)
        bb[nt] = *(const float2*)&bias[n0 + wn + nt * 8 + fc];

#pragma unroll
    for (int mt = 0; mt < 4; mt++) {
        const int mA = m0 + wm + mt * 16 + fr;
        const int mB = mA + 8;
#pragma unroll
        for (int nt = 0; nt < 4; nt++) {
            const int col = n0 + wn + nt * 8 + fc;
            float2 vA = make_float2(acc[mt][nt][0] + bb[nt].x,
                                    acc[mt][nt][1] + bb[nt].y);
            float2 vB = make_float2(acc[mt][nt][2] + bb[nt].x,
                                    acc[mt][nt][3] + bb[nt].y);
            float *pA, *pB;
            if (!scatter) {
                pA = Y + (size_t)mA * N_TOT + col;
                pB = Y + (size_t)mB * N_TOT + col;
            } else {
                const int h = col >> 6, d = col & 63;  // 2-col pair within one head
                const int bA = mA >> 11, sA = mA & 2047;
                const int bB = mB >> 11, sB = mB & 2047;
                pA = Y + ((size_t)((bA * NH + h) * SEQ + sA)) * HD + d;
                pB = Y + ((size_t)((bB * NH + h) * SEQ + sB)) * HD + d;
            }
            *(float2*)pA = vA;
            *(float2*)pB = vB;
        }
    }
}

// Fused QKV projection (tensor-pipe mma.sync): blockIdx.z selects {Q,K,V}.
__global__ __launch_bounds__(256, 2)
void qkv_mma_kernel(const float* __restrict__ q_in, const float* __restrict__ k_in,
                    const float* __restrict__ v_in,
                    const float* __restrict__ Wq, const float* __restrict__ bq,
                    const float* __restrict__ Wk, const float* __restrict__ bk,
                    const float* __restrict__ Wv, const float* __restrict__ bv,
                    float* __restrict__ Qo, float* __restrict__ Ko,
                    float* __restrict__ Vo)
{
    const int which = blockIdx.z;
    const float* X;  const float* W;  const float* bias;  float* Y;
    if (which == 0)      { X = q_in; W = Wq; bias = bq; Y = Qo; }
    else if (which == 1) { X = k_in; W = Wk; bias = bk; Y = Ko; }
    else                 { X = v_in; W = Wv; bias = bv; Y = Vo; }
    mma_gemm_tile(X, W, bias, Y, blockIdx.y * 128, blockIdx.x * 128, true);
}

__global__ __launch_bounds__(256, 2)
void out_mma_kernel(const float* __restrict__ X, const float* __restrict__ W,
                    const float* __restrict__ bias, float* __restrict__ Y)
{
    mma_gemm_tile(X, W, bias, Y, blockIdx.y * 128, blockIdx.x * 128, false);
}

// ---------------------------------------------------------------------------
// Flash attention (fp32, FFMA2) — unchanged from the measured R10 kernel.
// ---------------------------------------------------------------------------
__global__ __launch_bounds__(256)
void flash_attn_kernel(const float* __restrict__ Q, const float* __restrict__ K,
                       const float* __restrict__ V, const int* __restrict__ mask,
                       float* __restrict__ Xb)
{
    extern __shared__ float smf[];
    float* Qs = smf;                  // 64*68
    float* Ks = Qs + 64 * 68;         // 64*68
    float* Vs = Ks + 64 * 68;         // 64*64  [kk][d]
    float* Ps = Vs + 64 * 64;         // 64*64  [q][kk]
    int*   Mk = (int*)(Ps + 64 * 64); // 64

    const int tid = threadIdx.x;
    const int tx = tid & 15;
    const int ty = tid >> 4;
    const int bh = blockIdx.y;
    const int b  = bh >> 4;
    const int h  = bh & 15;
    const int q0 = blockIdx.x * 64;

    const float* Qg = Q + ((size_t)bh * SEQ + q0) * HD;
    const float* Kg = K + (size_t)bh * SEQ * HD;
    const float* Vg = V + (size_t)bh * SEQ * HD;
    const int*   mb = mask + b * SEQ;

    for (int i = tid; i < 64 * 64; i += 256) {
        const int q = i >> 6, d = i & 63;
        Qs[d * 68 + q] = Qg[i] * 0.125f;
    }

    u64 o2[4][2];
    float mr[4], lr[4];
#pragma unroll
    for (int i = 0; i < 4; i++) {
        mr[i] = -INFINITY; lr[i] = 0.f;
        o2[i][0] = 0ULL; o2[i][1] = 0ULL;
    }

    for (int kt = 0; kt < SEQ / 64; kt++) {
        const float* Ktile = Kg + (size_t)kt * 64 * HD;
        const float4* Vtile4 = (const float4*)(Vg + (size_t)kt * 64 * HD);
        __syncthreads();
        for (int i = tid; i < 64 * 64; i += 256) {
            const int r = i >> 6, d = i & 63;
            Ks[d * 68 + r] = Ktile[i];
        }
        for (int i = tid; i < 64 * 16; i += 256) {
            ((float4*)Vs)[i] = Vtile4[i];
        }
        if (tid < 64) Mk[tid] = mb[kt * 64 + tid];
        __syncthreads();

        u64 s2[4][2];
#pragma unroll
        for (int i = 0; i < 4; i++) { s2[i][0] = 0ULL; s2[i][1] = 0ULL; }

#pragma unroll 8
        for (int d = 0; d < 64; d++) {
            float4 a = *(const float4*)&Qs[d * 68 + ty * 4];
            ulonglong2 k2 = *(const ulonglong2*)&Ks[d * 68 + tx * 4];
            u64 ap;
            PACK2(ap, a.x); FFMA2(s2[0][0], ap, k2.x); FFMA2(s2[0][1], ap, k2.y);
            PACK2(ap, a.y); FFMA2(s2[1][0], ap, k2.x); FFMA2(s2[1][1], ap, k2.y);
            PACK2(ap, a.z); FFMA2(s2[2][0], ap, k2.x); FFMA2(s2[2][1], ap, k2.y);
            PACK2(ap, a.w); FFMA2(s2[3][0], ap, k2.x); FFMA2(s2[3][1], ap, k2.y);
        }

        float s[4][4];
#pragma unroll
        for (int i = 0; i < 4; i++) {
            unsigned r0, r1, r2, r3;
            UNPACK2(r0, r1, s2[i][0]);
            UNPACK2(r2, r3, s2[i][1]);
            s[i][0] = __uint_as_float(r0);
            s[i][1] = __uint_as_float(r1);
            s[i][2] = __uint_as_float(r2);
            s[i][3] = __uint_as_float(r3);
        }

#pragma unroll
        for (int j = 0; j < 4; j++) {
            const bool keep = (Mk[tx * 4 + j] != 0);
#pragma unroll
            for (int i = 0; i < 4; i++)
                s[i][j] = keep ? s[i][j] : -1.0e10f;
        }

#pragma unroll
        for (int i = 0; i < 4; i++) {
            float tm = fmaxf(fmaxf(s[i][0], s[i][1]), fmaxf(s[i][2], s[i][3]));
            tm = fmaxf(tm, __shfl_xor_sync(0xffffffffu, tm, 1));
            tm = fmaxf(tm, __shfl_xor_sync(0xffffffffu, tm, 2));
            tm = fmaxf(tm, __shfl_xor_sync(0xffffffffu, tm, 4));
            tm = fmaxf(tm, __shfl_xor_sync(0xffffffffu, tm, 8));
            const float mn = fmaxf(mr[i], tm);
            const float alpha = __expf(mr[i] - mn);
            mr[i] = mn;
            float rs = 0.f;
#pragma unroll
            for (int j = 0; j < 4; j++) {
                const float p = __expf(s[i][j] - mn);
                s[i][j] = p;
                rs += p;
            }
            rs += __shfl_xor_sync(0xffffffffu, rs, 1);
            rs += __shfl_xor_sync(0xffffffffu, rs, 2);
            rs += __shfl_xor_sync(0xffffffffu, rs, 4);
            rs += __shfl_xor_sync(0xffffffffu, rs, 8);
            lr[i] = lr[i] * alpha + rs;
            u64 al;
            PACK2(al, alpha);
            MUL2(o2[i][0], al);
            MUL2(o2[i][1], al);
            *(float4*)&Ps[(ty * 4 + i) * 64 + tx * 4] =
                make_float4(s[i][0], s[i][1], s[i][2], s[i][3]);
        }
        __syncthreads();

#pragma unroll 8
        for (int kk = 0; kk < 64; kk++) {
            ulonglong2 v2 = *(const ulonglong2*)&Vs[kk * 64 + tx * 4];
            const float p0 = Ps[(ty * 4 + 0) * 64 + kk];
            const float p1 = Ps[(ty * 4 + 1) * 64 + kk];
            const float p2 = Ps[(ty * 4 + 2) * 64 + kk];
            const float p3 = Ps[(ty * 4 + 3) * 64 + kk];
            u64 pp;
            PACK2(pp, p0); FFMA2(o2[0][0], pp, v2.x); FFMA2(o2[0][1], pp, v2.y);
            PACK2(pp, p1); FFMA2(o2[1][0], pp, v2.x); FFMA2(o2[1][1], pp, v2.y);
            PACK2(pp, p2); FFMA2(o2[2][0], pp, v2.x); FFMA2(o2[2][1], pp, v2.y);
            PACK2(pp, p3); FFMA2(o2[3][0], pp, v2.x); FFMA2(o2[3][1], pp, v2.y);
        }
    }

#pragma unroll
    for (int i = 0; i < 4; i++) {
        const float inv = 1.0f / lr[i];
        unsigned r0, r1, r2, r3;
        UNPACK2(r0, r1, o2[i][0]);
        UNPACK2(r2, r3, o2[i][1]);
        const int q = q0 + ty * 4 + i;
        float* p = Xb + ((size_t)(b * SEQ + q)) * N_TOT + h * HD + tx * 4;
        *(float4*)p = make_float4(__uint_as_float(r0) * inv,
                                  __uint_as_float(r1) * inv,
                                  __uint_as_float(r2) * inv,
                                  __uint_as_float(r3) * inv);
    }
}

// ---------------------------------------------------------------------------
// Launch (no static guards; all calls graph-capture-safe).
// ---------------------------------------------------------------------------
extern "C" void kernel_launch(void* const* d_in, const int* in_sizes, int n_in,
                              void* d_out, int out_size)
{
    const float* q    = (const float*)d_in[0];
    const float* k    = (const float*)d_in[1];
    const float* v    = (const float*)d_in[2];
    const int*   mask = (const int*)  d_in[3];
    const float* Wq   = (const float*)d_in[4];
    const float* bq   = (const float*)d_in[5];
    const float* Wk   = (const float*)d_in[6];
    const float* bk   = (const float*)d_in[7];
    const float* Wv   = (const float*)d_in[8];
    const float* bv   = (const float*)d_in[9];
    const float* Wo   = (const float*)d_in[10];
    const float* bo   = (const float*)d_in[11];
    float* out = (float*)d_out;

    void *pq, *pk, *pv, *px;
    cudaGetSymbolAddress(&pq, g_Q);
    cudaGetSymbolAddress(&pk, g_K);
    cudaGetSymbolAddress(&pv, g_V);
    cudaGetSymbolAddress(&px, g_X);

    cudaFuncSetAttribute(qkv_mma_kernel,
                         cudaFuncAttributeMaxDynamicSharedMemorySize, MM_TOTAL);
    cudaFuncSetAttribute(out_mma_kernel,
                         cudaFuncAttributeMaxDynamicSharedMemorySize, MM_TOTAL);
    const int flash_smem = (2 * 64 * 68 + 2 * 64 * 64) * 4 + 64 * 4;  // ~67.8 KB
    cudaFuncSetAttribute(flash_attn_kernel,
                         cudaFuncAttributeMaxDynamicSharedMemorySize, flash_smem);

    dim3 gqkv(N_TOT / 128, M_TOT / 128, 3);   // (8, 64, 3)
    qkv_mma_kernel<<<gqkv, 256, MM_TOTAL>>>(q, k, v, Wq, bq, Wk, bk, Wv, bv,
                                            (float*)pq, (float*)pk, (float*)pv);

    flash_attn_kernel<<<dim3(SEQ / 64, NB * NH), 256, flash_smem>>>(
        (const float*)pq, (const float*)pk, (const float*)pv, mask, (float*)px);

    dim3 go(N_TOT / 128, M_TOT / 128);        // (8, 64)
    out_mma_kernel<<<go, 256, MM_TOTAL>>>((const float*)px, Wo, bo, out);
}